// round 16
// baseline (speedup 1.0000x reference)
#include <cuda_runtime.h>
#include <cuda_fp16.h>
#include <cstdint>
#include <math.h>

#define Bsz 32
#define Tsz 512
#define DIsz 512
#define Hsz 512
#define G4 2048
#define G5 2560
#define NCTA 148
#define NTHR 512
#define BTHn ((size_t)32*512*512)

typedef unsigned int uint;
typedef unsigned short ushort;

// ---- static device scratch ----
static __device__ __align__(16) ushort g_hh[(size_t)4*512*32*512];   // h fp16 [l][t][b][k]
static __device__ float g_c[(size_t)4*512*32*512];                   // c fp32 [l][t][b][j]
static __device__ float g_xt[(size_t)512*2048*32];                   // [t][rowp][b]
static __device__ __align__(16) uint g_wA0[(size_t)16*8*32*128];     // L0 frags
static __device__ __align__(16) uint g_wAca[(size_t)132*8*32*128];   // CA frags
static __device__ unsigned g_flagH[4*64*32];                         // h-ready flags
static __device__ unsigned g_flagC[4*64*32];                         // c/out-ready flags

__device__ __forceinline__ float sigf(float x) {
    return __fdividef(1.0f, 1.0f + __expf(-x));
}
__device__ __forceinline__ float tanhef(float x) {
    return __fdividef(2.0f, 1.0f + __expf(-2.0f * x)) - 1.0f;
}
__device__ __forceinline__ ushort f16of(float w) {
    return __half_as_ushort(__float2half_rn(w));
}
__device__ __forceinline__ unsigned ld_acq(const unsigned* p) {
    unsigned v;
    asm volatile("ld.acquire.gpu.global.u32 %0, [%1];" : "=r"(v) : "l"(p) : "memory");
    return v;
}
__device__ __forceinline__ void st_rel(unsigned* p, unsigned v) {
    asm volatile("st.release.gpu.global.u32 [%0], %1;" :: "l"(p), "r"(v) : "memory");
}
__device__ __forceinline__ void poll_flags(const unsigned* base, int nc, unsigned target) {
    int lane = threadIdx.x & 31;
    const unsigned* p1 = base + lane * 32;
    const unsigned* p2 = base + (lane + 32) * 32;
    bool n1 = lane < nc, n2 = (lane + 32) < nc;
    bool ok;
    do {
        ok = true;
        if (n1 && ld_acq(p1) < target) ok = false;
        if (n2 && ld_acq(p2) < target) ok = false;
    } while (__all_sync(0xffffffffu, ok) == 0);
}

__device__ __forceinline__ void mma_f16(float* d, const uint4& a, uint b0, uint b1) {
    asm volatile(
        "mma.sync.aligned.m16n8k16.row.col.f32.f16.f16.f32 "
        "{%0,%1,%2,%3},{%4,%5,%6,%7},{%8,%9},{%0,%1,%2,%3};"
        : "+f"(d[0]), "+f"(d[1]), "+f"(d[2]), "+f"(d[3])
        : "r"(a.x), "r"(a.y), "r"(a.z), "r"(a.w), "r"(b0), "r"(b1));
}
__device__ __forceinline__ void ldsm_x4(uint& r0, uint& r1, uint& r2, uint& r3, uint addr) {
    asm volatile(
        "ldmatrix.sync.aligned.m8n8.x4.shared.b16 {%0,%1,%2,%3}, [%4];"
        : "=r"(r0), "=r"(r1), "=r"(r2), "=r"(r3) : "r"(addr));
}
#define BARX(ID) asm volatile("bar.sync %0, 256;" :: "r"(ID) : "memory")

static __device__ __host__ __forceinline__ void cta_params(int ci, int& nj, int& j0) {
    if (ci < 28) { nj = 12; j0 = ci * 12; }
    else         { nj = 11; j0 = 336 + (ci - 28) * 11; }
}

// ---------------- weight fragment packing + flag reset ----------------
__global__ void __launch_bounds__(256) k_fill(const float* __restrict__ w_hh,
                                              const float* __restrict__ ca_w)
{
    size_t stride = (size_t)gridDim.x * blockDim.x;
    size_t i0 = (size_t)blockIdx.x * blockDim.x + threadIdx.x;
    for (size_t e = i0; e < 4 * 64 * 32; e += stride) { g_flagH[e] = 0u; g_flagC[e] = 0u; }

    const size_t N0 = (size_t)16*8*32*128;
    for (size_t e = i0; e < N0; e += stride) {
        int reg = (int)(e & 3), lane = (int)((e >> 2) & 31), ks = (int)((e >> 7) & 31);
        int mw = (int)((e >> 12) & 7), cta = (int)(e >> 15);
        int gr = lane >> 2, c0 = (lane & 3) * 2;
        int slot = mw * 16 + gr + (reg & 1) * 8;
        int kk = ks * 16 + c0 + ((reg >> 1) & 1) * 8;
        int row = (slot >> 5) * 512 + cta * 32 + (slot & 31);
        float w0 = w_hh[(size_t)row * 512 + kk];
        float w1 = w_hh[(size_t)row * 512 + kk + 1];
        g_wA0[e] = (uint)f16of(w0) | ((uint)f16of(w1) << 16);
    }
    const size_t NC = (size_t)132*8*32*128;
    for (size_t e = i0; e < NC; e += stride) {
        int reg = (int)(e & 3), lane = (int)((e >> 2) & 31), ks = (int)((e >> 7) & 31);
        int mk = (int)((e >> 12) & 7), lc = (int)(e >> 15);
        int mw = mk >> 1, kw = mk & 1;
        int gr = lane >> 2, c0 = (lane & 3) * 2;
        int slot = mw * 16 + gr + (reg & 1) * 8;
        int kk = kw * 512 + ks * 16 + c0 + ((reg >> 1) & 1) * 8;
        int ci = lc % 44, l = lc / 44;
        int nj, j0; cta_params(ci, nj, j0);
        float w0 = 0.0f, w1 = 0.0f;
        if (slot < 5 * nj) {
            int g = slot / nj, jj = slot - g * nj;
            int row = g * 512 + j0 + jj;
            w0 = ca_w[((size_t)l * G5 + row) * 1024 + kk];
            w1 = ca_w[((size_t)l * G5 + row) * 1024 + kk + 1];
        }
        g_wAca[e] = (uint)f16of(w0) | ((uint)f16of(w1) << 16);
    }
}

// ---------------- xproj = x @ w_ih.T + bias, stored [t][rowp][b] ----------------
__global__ void __launch_bounds__(256) k_xproj(
    const float* __restrict__ x, const float* __restrict__ w_ih,
    const float* __restrict__ b_ih, const float* __restrict__ b_hh)
{
    __shared__ float As[16][65];
    __shared__ float Bs[16][65];
    const int bm = blockIdx.y * 64, bn = blockIdx.x * 64;
    const int tid = threadIdx.x;
    const int tr = (tid >> 4) << 2, tc = (tid & 15) << 2;
    float acc[4][4] = {};
    for (int k0 = 0; k0 < DIsz; k0 += 16) {
        #pragma unroll
        for (int i0 = 0; i0 < 4; i0++) {
            int i = i0 * 256 + tid;
            int mm = i >> 4, kk = i & 15;
            int m = bm + mm, tt = m >> 5, bb = m & 31;
            As[kk][mm] = x[((size_t)bb * Tsz + tt) * DIsz + (k0 + kk)];
            Bs[kk][mm] = w_ih[(size_t)(bn + mm) * DIsz + (k0 + kk)];
        }
        __syncthreads();
        #pragma unroll
        for (int kk = 0; kk < 16; kk++) {
            float a[4] = {As[kk][tr], As[kk][tr+1], As[kk][tr+2], As[kk][tr+3]};
            float b[4] = {Bs[kk][tc], Bs[kk][tc+1], Bs[kk][tc+2], Bs[kk][tc+3]};
            #pragma unroll
            for (int i = 0; i < 4; i++)
                #pragma unroll
                for (int j = 0; j < 4; j++)
                    acc[i][j] = fmaf(a[i], b[j], acc[i][j]);
        }
        __syncthreads();
    }
    #pragma unroll
    for (int i = 0; i < 4; i++) {
        int m = bm + tr + i, tt = m >> 5, bb = m & 31;
        #pragma unroll
        for (int j = 0; j < 4; j++) {
            int n = bn + tc + j;
            int g = n >> 9, cd = (n >> 5) & 15, jj = n & 31;
            g_xt[((size_t)tt * 2048 + cd * 128 + g * 32 + jj) * 32 + bb]
                = acc[i][j] + b_ih[n] + b_hh[n];
        }
    }
}

// ---------------- persistent self-timed LSTM, smem-resident weights ----------------
__global__ void __launch_bounds__(NTHR, 1) k_wave(
    const float* __restrict__ ca_b, float* __restrict__ out)
{
    extern __shared__ char smx[];

    const int tid  = threadIdx.x;
    const int lane = tid & 31;
    const int wid  = tid >> 5;
    const int cta  = blockIdx.x;
    const int gr = lane >> 2, c0 = (lane & 3) * 2;

    int layer, j0, nj, ci = 0;
    if (cta < 16) { layer = 0; nj = 32; j0 = cta * 32; }
    else {
        int r = cta - 16;
        layer = 1 + r / 44;
        ci = r % 44;
        cta_params(ci, nj, j0);
    }
    const int K  = (layer == 0) ? 512 : 1024;
    const int rs = K + 8;

    // dynamic smem layout: Bh | part(16896B) | cring | weights(131072B)
    ushort* Bh = (ushort*)smx;
    const size_t off_part = (size_t)32 * rs * 2;
    float* part  = (float*)(smx + off_part);
    float* cring = (float*)(smx + off_part + 16896);
    const int CR = (layer == 0) ? 1024 : nj * 32;
    uint4* wS4 = (uint4*)(smx + off_part + 16896 + ((layer == 0) ? 8192 : 3072));
    const int PSTRC = 2112;   // CA partial region stride (floats)
    const uint bb32 = (uint)__cvta_generic_to_shared(smx);

    // warp roles: L0: mw=wid>>1 (0..7), np=wid&1, kw=0
    //             CA: kw=wid>>3 (group), mw=(wid>>1)&3, np=wid&1
    int mw, np, kw;
    float bias0 = 0.0f, bias1 = 0.0f;
    if (layer == 0) {
        mw = wid >> 1; np = wid & 1; kw = 0;
    } else {
        kw = wid >> 3; mw = (wid >> 1) & 3; np = wid & 1;
        if (kw == 0) {
            const float* cb = ca_b + (size_t)(layer - 1) * G5;
            int s0 = mw * 16 + gr, s1 = s0 + 8;
            if (s0 < 5 * nj) bias0 = cb[(s0 / nj) * 512 + j0 + (s0 % nj)];
            if (s1 < 5 * nj) bias1 = cb[(s1 / nj) * 512 + j0 + (s1 % nj)];
        }
    }
    const int rgn = (layer == 0) ? mw : (mw * 2 + kw);
    const uint4* wpS = wS4 + (size_t)rgn * 1024 + lane;

    const int lrow = (np * 2 + ((lane >> 3) >> 1)) * 8 + (lane & 7);
    const uint ldsm_off = bb32 + (uint)(lrow * rs * 2 + ((lane >> 3) & 1) * 16);

    unsigned* myflagH = g_flagH + ((size_t)layer * 64 + (layer == 0 ? cta : ci)) * 32;
    unsigned* myflagC = g_flagC + ((size_t)layer * 64 + (layer == 0 ? cta : ci)) * 32;
    const unsigned* ownflagsH = g_flagH + ((size_t)layer * 64) * 32;
    const unsigned* lowflagsC = (layer > 0) ? g_flagC + ((size_t)(layer - 1) * 64) * 32 : nullptr;
    const int nc_low = (layer == 1) ? 16 : 44;
    const int nc_own = (layer == 0) ? 16 : 44;

    // ---- one-time: stage this CTA's weights into smem (fragment order) ----
    {
        const uint4* wg = (layer == 0)
            ? (const uint4*)g_wA0 + (size_t)cta * 8192
            : (const uint4*)g_wAca + (size_t)((layer - 1) * 44 + ci) * 8192;
        for (int i = tid; i < 8192; i += NTHR) wS4[i] = __ldg(wg + i);
    }
    __syncthreads();

    for (int t = 0; t < Tsz; ++t) {
        const bool active = !(t == 0 && (layer == 0 || kw == 1));
        float d[2][4];

        if (layer == 0) {
            if (wid == 0 && t > 0) poll_flags(ownflagsH, nc_own, (unsigned)t);
            __syncthreads();
            {
                const float* xb = g_xt + ((size_t)t * 2048 + cta * 128) * 32;
                int sl0 = mw * 16 + gr;
                #pragma unroll
                for (int ntp = 0; ntp < 2; ntp++) {
                    int bc = (np * 2 + ntp) * 8 + c0;
                    d[ntp][0] = __ldcg(xb + sl0 * 32 + bc);
                    d[ntp][1] = __ldcg(xb + sl0 * 32 + bc + 1);
                    d[ntp][2] = __ldcg(xb + (sl0 + 8) * 32 + bc);
                    d[ntp][3] = __ldcg(xb + (sl0 + 8) * 32 + bc + 1);
                }
            }
            {
                const uint4 zz = make_uint4(0, 0, 0, 0);
                for (int e = tid; e < 32 * 64; e += NTHR) {
                    int b = e >> 6, c = e & 63;
                    int k8 = c * 8;
                    uint4 vh = (t > 0)
                        ? __ldcg((const uint4*)(g_hh + (((size_t)(t - 1)) * 32 + b) * 512 + k8))
                        : zz;
                    *(uint4*)(Bh + b * rs + k8) = vh;
                }
            }
            __syncthreads();
        } else {
            #pragma unroll
            for (int ntp = 0; ntp < 2; ntp++) {
                d[ntp][0] = bias0; d[ntp][1] = bias0;
                d[ntp][2] = bias1; d[ntp][3] = bias1;
            }
            if (kw == 0) {
                if (wid == 0) poll_flags(lowflagsC, nc_low, (unsigned)(t + 1));
                BARX(1);
                for (int e = tid; e < 32 * 64; e += 256) {
                    int b = e >> 6, c = e & 63;
                    int k8 = c * 8;
                    uint4 vh = __ldcg((const uint4*)(
                        g_hh + (((size_t)(layer - 1) * Tsz + t) * 32 + b) * 512 + k8));
                    *(uint4*)(Bh + b * rs + k8) = vh;
                }
                BARX(1);
            } else {
                if (wid == 8 && t > 0) poll_flags(ownflagsH, nc_own, (unsigned)t);
                BARX(2);
                const uint4 zz = make_uint4(0, 0, 0, 0);
                for (int e = tid - 256; e < 32 * 64; e += 256) {
                    int b = e >> 6, c = e & 63;
                    int k8 = c * 8;
                    uint4 vh = (t > 0)
                        ? __ldcg((const uint4*)(
                              g_hh + (((size_t)layer * Tsz + (t - 1)) * 32 + b) * 512 + k8))
                        : zz;
                    *(uint4*)(Bh + b * rs + 512 + k8) = vh;
                }
                BARX(2);
            }
        }

        // ---- tensor-core GEMM: A from smem, B via ldmatrix ----
        const int kwbase = kw * 512;
        if (active) {
            #pragma unroll 4
            for (int ks = 0; ks < 32; ks++) {
                uint4 a = wpS[(size_t)ks * 32];
                uint b00, b01, b10, b11;
                ldsm_x4(b00, b01, b10, b11,
                        ldsm_off + (uint)((kwbase + ks * 16) * 2));
                mma_f16(d[0], a, b00, b01);
                mma_f16(d[1], a, b10, b11);
            }
        }
        {
            float* pp = part + (layer == 0 ? 0 : kw * PSTRC);
            #pragma unroll
            for (int ntp = 0; ntp < 2; ntp++) {
                int sl0 = mw * 16 + gr;
                int bc = (np * 2 + ntp) * 8 + c0;
                pp[sl0 * 33 + bc]       = d[ntp][0];
                pp[sl0 * 33 + bc + 1]   = d[ntp][1];
                pp[(sl0 + 8) * 33 + bc]     = d[ntp][2];
                pp[(sl0 + 8) * 33 + bc + 1] = d[ntp][3];
            }
        }
        __syncthreads();

        // ---- activation: h first, publish flagH early, then c/out, flagC ----
        {
            size_t so = (((size_t)layer * Tsz + t)) * 32;
            float*  cout = g_c  + so * 512;
            ushort* hho  = g_hh + so * 512;
            float* ccur = cring + (t & 1) * CR;
            float* cprv = cring + ((t & 1) ^ 1) * CR;
            if (layer == 0) {
                float cvv[2];
                #pragma unroll
                for (int n = 0; n < 2; n++) {
                    int it = tid + n * NTHR;
                    int b = it >> 5, jj = it & 31;
                    int j = cta * 32 + jj;
                    float i_ = part[(0 * 32 + jj) * 33 + b];
                    float f_ = part[(1 * 32 + jj) * 33 + b];
                    float gg = part[(2 * 32 + jj) * 33 + b];
                    float o_ = part[(3 * 32 + jj) * 33 + b];
                    float cp = (t > 0) ? cprv[it] : 0.0f;
                    float cv = sigf(i_) * tanhef(gg) + sigf(f_) * cp;
                    float hv = sigf(o_) * tanhef(cv);
                    ccur[it] = cv;
                    hho[(size_t)b * 512 + j] = f16of(hv);
                    cvv[n] = cv;
                }
                __syncthreads();
                if (tid == 0) st_rel(myflagH, (unsigned)(t + 1));
                #pragma unroll
                for (int n = 0; n < 2; n++) {
                    int it = tid + n * NTHR;
                    int b = it >> 5, jj = it & 31;
                    cout[(size_t)b * 512 + cta * 32 + jj] = cvv[n];
                }
                __syncthreads();
                if (tid == 0) st_rel(myflagC, (unsigned)(t + 1));
            } else {
                const float* clow = g_c + (((size_t)(layer - 1) * Tsz + t) * 32) * 512;
                float cvs = 0.0f, hvs = 0.0f;
                int b = 0, j = 0;
                const bool has = tid < nj * 32;
                if (has) {
                    int it = tid;
                    b = it / nj;
                    int jj = it - b * nj;
                    j = j0 + jj;
                    #define RED(SL, B) (part[(SL) * 33 + (B)] + part[PSTRC + (SL) * 33 + (B)])
                    float i_ = RED(0 * nj + jj, b);
                    float fp = RED(1 * nj + jj, b);
                    float fl = RED(2 * nj + jj, b);
                    float u_ = RED(3 * nj + jj, b);
                    float o_ = RED(4 * nj + jj, b);
                    #undef RED
                    float cp = (t > 0) ? cprv[it] : 0.0f;
                    float cl = __ldcg(clow + (size_t)b * 512 + j);
                    cvs = cp * sigf(fp + 1.0f) + cl * sigf(fl + 1.0f) + tanhef(u_) * sigf(i_);
                    hvs = sigf(o_) * tanhef(cvs);
                    ccur[it] = cvs;
                    hho[(size_t)b * 512 + j] = f16of(hvs);
                }
                __syncthreads();
                if (tid == 0) st_rel(myflagH, (unsigned)(t + 1));
                if (layer != 3) {
                    if (has) cout[(size_t)b * 512 + j] = cvs;
                    __syncthreads();
                    if (tid == 0) st_rel(myflagC, (unsigned)(t + 1));
                } else if (has) {
                    out[(size_t)b * Tsz * Hsz + (size_t)t * Hsz + j] = hvs;
                    out[BTHn + (size_t)b * Tsz * Hsz + (size_t)t * Hsz + j] = cvs;
                    if (t == Tsz - 1) {
                        out[2 * BTHn + (size_t)b * Hsz + j] = hvs;
                        out[2 * BTHn + (size_t)Bsz * Hsz + (size_t)b * Hsz + j] = cvs;
                    }
                }
            }
        }
    }
}

extern "C" void kernel_launch(void* const* d_in, const int* in_sizes, int n_in,
                              void* d_out, int out_size)
{
    const float* x    = (const float*)d_in[0];
    const float* w_ih = (const float*)d_in[1];
    const float* w_hh = (const float*)d_in[2];
    const float* b_ih = (const float*)d_in[3];
    const float* b_hh = (const float*)d_in[4];
    const float* ca_w = (const float*)d_in[5];
    const float* ca_b = (const float*)d_in[6];
    float* out = (float*)d_out;
    (void)in_sizes; (void)n_in; (void)out_size;

    k_fill<<<296, 256>>>(w_hh, ca_w);

    dim3 g(G4 / 64, (Tsz * Bsz) / 64);
    k_xproj<<<g, 256>>>(x, w_ih, b_ih, b_hh);

    // CA smem: 32*1032*2 + 16896 + 3072 + 131072 = 217088 bytes
    const int smem_bytes = 217088;
    cudaFuncSetAttribute(k_wave, cudaFuncAttributeMaxDynamicSharedMemorySize, smem_bytes);
    k_wave<<<NCTA, NTHR, smem_bytes>>>(ca_b, out);
}

// round 17
// speedup vs baseline: 1.0592x; 1.0592x over previous
#include <cuda_runtime.h>
#include <cuda_fp16.h>
#include <cstdint>
#include <math.h>

#define Bsz 32
#define Tsz 512
#define DIsz 512
#define Hsz 512
#define G4 2048
#define G5 2560
#define NCTA 148
#define NTHR 512
#define BTHn ((size_t)32*512*512)

typedef unsigned int uint;
typedef unsigned short ushort;

// ---- static device scratch ----
static __device__ __align__(16) ushort g_hh[(size_t)4*512*32*512];   // h fp16 [l][t][b][k]
static __device__ float g_c[(size_t)4*512*32*512];                   // c fp32 [l][t][b][j]
static __device__ float g_xt[(size_t)512*2048*32];                   // [t][rowp][b]
static __device__ __align__(16) uint g_wA0[(size_t)16*8*32*128];     // L0 frags
static __device__ __align__(16) uint g_wAca[(size_t)132*8*32*128];   // CA frags
static __device__ unsigned g_flagH[4*64*32];                         // h-ready flags
static __device__ unsigned g_flagC[4*64*32];                         // c-ready flags

#define PSTR 4224            // 128*33 floats per partial region
#define PART_OFF 66048       // bytes: B region = 32*1032 ushorts * 2B
#define CRING_OFF (PART_OFF + 2 * PSTR * 4)   // c ring: 2 x 1024 floats

__device__ __forceinline__ float sigf(float x) {
    return __fdividef(1.0f, 1.0f + __expf(-x));
}
__device__ __forceinline__ float tanhef(float x) {
    return __fdividef(2.0f, 1.0f + __expf(-2.0f * x)) - 1.0f;
}
__device__ __forceinline__ ushort f16of(float w) {
    return __half_as_ushort(__float2half_rn(w));
}
__device__ __forceinline__ unsigned ld_acq(const unsigned* p) {
    unsigned v;
    asm volatile("ld.acquire.gpu.global.u32 %0, [%1];" : "=r"(v) : "l"(p) : "memory");
    return v;
}
__device__ __forceinline__ void st_rel(unsigned* p, unsigned v) {
    asm volatile("st.release.gpu.global.u32 [%0], %1;" :: "l"(p), "r"(v) : "memory");
}
__device__ __forceinline__ void poll_flags(const unsigned* base, int nc, unsigned target) {
    int lane = threadIdx.x & 31;
    const unsigned* p1 = base + lane * 32;
    const unsigned* p2 = base + (lane + 32) * 32;
    bool n1 = lane < nc, n2 = (lane + 32) < nc;
    bool ok;
    do {
        ok = true;
        if (n1 && ld_acq(p1) < target) ok = false;
        if (n2 && ld_acq(p2) < target) ok = false;
    } while (__all_sync(0xffffffffu, ok) == 0);
}

__device__ __forceinline__ void mma_f16(float* d, const uint4& a, uint b0, uint b1) {
    asm volatile(
        "mma.sync.aligned.m16n8k16.row.col.f32.f16.f16.f32 "
        "{%0,%1,%2,%3},{%4,%5,%6,%7},{%8,%9},{%0,%1,%2,%3};"
        : "+f"(d[0]), "+f"(d[1]), "+f"(d[2]), "+f"(d[3])
        : "r"(a.x), "r"(a.y), "r"(a.z), "r"(a.w), "r"(b0), "r"(b1));
}
__device__ __forceinline__ void ldsm_x4(uint& r0, uint& r1, uint& r2, uint& r3, uint addr) {
    asm volatile(
        "ldmatrix.sync.aligned.m8n8.x4.shared.b16 {%0,%1,%2,%3}, [%4];"
        : "=r"(r0), "=r"(r1), "=r"(r2), "=r"(r3) : "r"(addr));
}
#define BARX(ID) asm volatile("bar.sync %0, 256;" :: "r"(ID) : "memory")

static __device__ __host__ __forceinline__ void cta_params(int ci, int& nj, int& j0) {
    if (ci < 28) { nj = 12; j0 = ci * 12; }
    else         { nj = 11; j0 = 336 + (ci - 28) * 11; }
}

// ---------------- weight fragment packing + flag reset ----------------
__global__ void __launch_bounds__(256) k_fill(const float* __restrict__ w_hh,
                                              const float* __restrict__ ca_w)
{
    size_t stride = (size_t)gridDim.x * blockDim.x;
    size_t i0 = (size_t)blockIdx.x * blockDim.x + threadIdx.x;
    for (size_t e = i0; e < 4 * 64 * 32; e += stride) { g_flagH[e] = 0u; g_flagC[e] = 0u; }

    const size_t N0 = (size_t)16*8*32*128;
    for (size_t e = i0; e < N0; e += stride) {
        int reg = (int)(e & 3), lane = (int)((e >> 2) & 31), ks = (int)((e >> 7) & 31);
        int mw = (int)((e >> 12) & 7), cta = (int)(e >> 15);
        int gr = lane >> 2, c0 = (lane & 3) * 2;
        int slot = mw * 16 + gr + (reg & 1) * 8;
        int kk = ks * 16 + c0 + ((reg >> 1) & 1) * 8;
        int row = (slot >> 5) * 512 + cta * 32 + (slot & 31);
        float w0 = w_hh[(size_t)row * 512 + kk];
        float w1 = w_hh[(size_t)row * 512 + kk + 1];
        g_wA0[e] = (uint)f16of(w0) | ((uint)f16of(w1) << 16);
    }
    const size_t NC = (size_t)132*8*32*128;
    for (size_t e = i0; e < NC; e += stride) {
        int reg = (int)(e & 3), lane = (int)((e >> 2) & 31), ks = (int)((e >> 7) & 31);
        int mk = (int)((e >> 12) & 7), lc = (int)(e >> 15);
        int mw = mk >> 1, kw = mk & 1;
        int gr = lane >> 2, c0 = (lane & 3) * 2;
        int slot = mw * 16 + gr + (reg & 1) * 8;
        int kk = kw * 512 + ks * 16 + c0 + ((reg >> 1) & 1) * 8;
        int ci = lc % 44, l = lc / 44;
        int nj, j0; cta_params(ci, nj, j0);
        float w0 = 0.0f, w1 = 0.0f;
        if (slot < 5 * nj) {
            int g = slot / nj, jj = slot - g * nj;
            int row = g * 512 + j0 + jj;
            w0 = ca_w[((size_t)l * G5 + row) * 1024 + kk];
            w1 = ca_w[((size_t)l * G5 + row) * 1024 + kk + 1];
        }
        g_wAca[e] = (uint)f16of(w0) | ((uint)f16of(w1) << 16);
    }
}

// ---------------- xproj = x @ w_ih.T + bias, stored [t][rowp][b] ----------------
__global__ void __launch_bounds__(256) k_xproj(
    const float* __restrict__ x, const float* __restrict__ w_ih,
    const float* __restrict__ b_ih, const float* __restrict__ b_hh)
{
    __shared__ float As[16][65];
    __shared__ float Bs[16][65];
    const int bm = blockIdx.y * 64, bn = blockIdx.x * 64;
    const int tid = threadIdx.x;
    const int tr = (tid >> 4) << 2, tc = (tid & 15) << 2;
    float acc[4][4] = {};
    for (int k0 = 0; k0 < DIsz; k0 += 16) {
        #pragma unroll
        for (int i0 = 0; i0 < 4; i0++) {
            int i = i0 * 256 + tid;
            int mm = i >> 4, kk = i & 15;
            int m = bm + mm, tt = m >> 5, bb = m & 31;
            As[kk][mm] = x[((size_t)bb * Tsz + tt) * DIsz + (k0 + kk)];
            Bs[kk][mm] = w_ih[(size_t)(bn + mm) * DIsz + (k0 + kk)];
        }
        __syncthreads();
        #pragma unroll
        for (int kk = 0; kk < 16; kk++) {
            float a[4] = {As[kk][tr], As[kk][tr+1], As[kk][tr+2], As[kk][tr+3]};
            float b[4] = {Bs[kk][tc], Bs[kk][tc+1], Bs[kk][tc+2], Bs[kk][tc+3]};
            #pragma unroll
            for (int i = 0; i < 4; i++)
                #pragma unroll
                for (int j = 0; j < 4; j++)
                    acc[i][j] = fmaf(a[i], b[j], acc[i][j]);
        }
        __syncthreads();
    }
    #pragma unroll
    for (int i = 0; i < 4; i++) {
        int m = bm + tr + i, tt = m >> 5, bb = m & 31;
        #pragma unroll
        for (int j = 0; j < 4; j++) {
            int n = bn + tc + j;
            int g = n >> 9, cd = (n >> 5) & 15, jj = n & 31;
            g_xt[((size_t)tt * 2048 + cd * 128 + g * 32 + jj) * 32 + bb]
                = acc[i][j] + b_ih[n] + b_hh[n];
        }
    }
}

// ---------------- persistent self-timed LSTM, warp-group-specialized ----------------
__global__ void __launch_bounds__(NTHR, 1) k_wave(
    const float* __restrict__ ca_b, float* __restrict__ out)
{
    extern __shared__ char smx[];

    const int tid  = threadIdx.x;
    const int lane = tid & 31;
    const int wid  = tid >> 5;
    const int cta  = blockIdx.x;
    const int gr = lane >> 2, c0 = (lane & 3) * 2;

    int layer, j0, nj, ci = 0;
    if (cta < 16) { layer = 0; nj = 32; j0 = cta * 32; }
    else {
        int r = cta - 16;
        layer = 1 + r / 44;
        ci = r % 44;
        cta_params(ci, nj, j0);
    }
    const int K  = (layer == 0) ? 512 : 1024;
    const int rs = K + 8;
    ushort* Bh = (ushort*)smx;
    float* part  = (float*)(smx + PART_OFF);
    float* cring = (float*)(smx + CRING_OFF);
    const uint bb32 = (uint)__cvta_generic_to_shared(smx);

    // warp roles: L0: mw=wid>>1 (0..7), np=wid&1, kw=0
    //             CA: kw=wid>>3 (group), mw=(wid>>1)&3, np=wid&1
    int mw, np, kw;
    const uint4* wp4;
    float bias0 = 0.0f, bias1 = 0.0f;
    if (layer == 0) {
        mw = wid >> 1; np = wid & 1; kw = 0;
        wp4 = (const uint4*)g_wA0 + ((size_t)(cta * 8 + mw)) * 1024 + lane;
    } else {
        kw = wid >> 3; mw = (wid >> 1) & 3; np = wid & 1;
        wp4 = (const uint4*)g_wAca + ((size_t)(((layer - 1) * 44 + ci) * 8 + mw * 2 + kw)) * 1024 + lane;
        if (kw == 0) {
            const float* cb = ca_b + (size_t)(layer - 1) * G5;
            int s0 = mw * 16 + gr, s1 = s0 + 8;
            if (s0 < 5 * nj) bias0 = cb[(s0 / nj) * 512 + j0 + (s0 % nj)];
            if (s1 < 5 * nj) bias1 = cb[(s1 / nj) * 512 + j0 + (s1 % nj)];
        }
    }
    const int lrow = (np * 2 + ((lane >> 3) >> 1)) * 8 + (lane & 7);
    const uint ldsm_off = bb32 + (uint)(lrow * rs * 2 + ((lane >> 3) & 1) * 16);
    const int kwbase = kw * 512;
    unsigned* myflagH = g_flagH + ((size_t)layer * 64 + (layer == 0 ? cta : ci)) * 32;
    unsigned* myflagC = g_flagC + ((size_t)layer * 64 + (layer == 0 ? cta : ci)) * 32;
    const unsigned* ownflagsH = g_flagH + ((size_t)layer * 64) * 32;
    const unsigned* lowflagsC = (layer > 0) ? g_flagC + ((size_t)(layer - 1) * 64) * 32 : nullptr;
    const int nc_low = (layer == 1) ? 16 : 44;
    const int nc_own = (layer == 0) ? 16 : 44;

    for (int t = 0; t < Tsz; ++t) {
        const bool active = !(t == 0 && (layer == 0 || kw == 1));

        uint4 w0r, w1r, w2r, w3r;
        if (active) {
            w0r = __ldg(wp4);
            w1r = __ldg(wp4 + 1 * 32);
            w2r = __ldg(wp4 + 2 * 32);
            w3r = __ldg(wp4 + 3 * 32);
        }

        float d[2][4];

        if (layer == 0) {
            if (wid == 0 && t > 0) poll_flags(ownflagsH, nc_own, (unsigned)t);
            __syncthreads();
            {
                const float* xb = g_xt + ((size_t)t * 2048 + cta * 128) * 32;
                int sl0 = mw * 16 + gr;
                #pragma unroll
                for (int ntp = 0; ntp < 2; ntp++) {
                    int bc = (np * 2 + ntp) * 8 + c0;
                    d[ntp][0] = __ldcg(xb + sl0 * 32 + bc);
                    d[ntp][1] = __ldcg(xb + sl0 * 32 + bc + 1);
                    d[ntp][2] = __ldcg(xb + (sl0 + 8) * 32 + bc);
                    d[ntp][3] = __ldcg(xb + (sl0 + 8) * 32 + bc + 1);
                }
            }
            {
                const uint4 zz = make_uint4(0, 0, 0, 0);
                for (int e = tid; e < 32 * 64; e += NTHR) {
                    int b = e >> 6, c = e & 63;
                    int k8 = c * 8;
                    uint4 vh = (t > 0)
                        ? __ldcg((const uint4*)(g_hh + (((size_t)(t - 1)) * 32 + b) * 512 + k8))
                        : zz;
                    *(uint4*)(Bh + b * rs + k8) = vh;
                }
            }
            __syncthreads();
        } else {
            #pragma unroll
            for (int ntp = 0; ntp < 2; ntp++) {
                d[ntp][0] = bias0; d[ntp][1] = bias0;
                d[ntp][2] = bias1; d[ntp][3] = bias1;
            }
            if (kw == 0) {
                if (wid == 0) poll_flags(lowflagsC, nc_low, (unsigned)(t + 1));
                BARX(1);
                for (int e = tid; e < 32 * 64; e += 256) {
                    int b = e >> 6, c = e & 63;
                    int k8 = c * 8;
                    uint4 vh = __ldcg((const uint4*)(
                        g_hh + (((size_t)(layer - 1) * Tsz + t) * 32 + b) * 512 + k8));
                    *(uint4*)(Bh + b * rs + k8) = vh;
                }
                BARX(1);
            } else {
                if (wid == 8 && t > 0) poll_flags(ownflagsH, nc_own, (unsigned)t);
                BARX(2);
                const uint4 zz = make_uint4(0, 0, 0, 0);
                for (int e = tid - 256; e < 32 * 64; e += 256) {
                    int b = e >> 6, c = e & 63;
                    int k8 = c * 8;
                    uint4 vh = (t > 0)
                        ? __ldcg((const uint4*)(
                              g_hh + (((size_t)layer * Tsz + (t - 1)) * 32 + b) * 512 + k8))
                        : zz;
                    *(uint4*)(Bh + b * rs + 512 + k8) = vh;
                }
                BARX(2);
            }
        }

        // ---- tensor-core GEMM: 1 m-tile x 2 nt x 32 ks per warp ----
        if (active) {
            #pragma unroll
            for (int ks = 0; ks < 32; ks++) {
                uint4 a;
                switch (ks & 3) {
                    case 0: a = w0r; if (ks + 4 < 32) w0r = __ldg(wp4 + (ks + 4) * 32); break;
                    case 1: a = w1r; if (ks + 4 < 32) w1r = __ldg(wp4 + (ks + 4) * 32); break;
                    case 2: a = w2r; if (ks + 4 < 32) w2r = __ldg(wp4 + (ks + 4) * 32); break;
                    default: a = w3r; if (ks + 4 < 32) w3r = __ldg(wp4 + (ks + 4) * 32); break;
                }
                uint b00, b01, b10, b11;
                ldsm_x4(b00, b01, b10, b11,
                        ldsm_off + (uint)((kwbase + ks * 16) * 2));
                mma_f16(d[0], a, b00, b01);
                mma_f16(d[1], a, b10, b11);
            }
        }
        {
            float* pp = part + kw * PSTR;
            #pragma unroll
            for (int ntp = 0; ntp < 2; ntp++) {
                int sl0 = mw * 16 + gr;
                int bc = (np * 2 + ntp) * 8 + c0;
                pp[sl0 * 33 + bc]       = d[ntp][0];
                pp[sl0 * 33 + bc + 1]   = d[ntp][1];
                pp[(sl0 + 8) * 33 + bc]     = d[ntp][2];
                pp[(sl0 + 8) * 33 + bc + 1] = d[ntp][3];
            }
        }
        __syncthreads();

        // ---- activation: h stores first -> flagH, then c stores -> flagC ----
        {
            size_t so = (((size_t)layer * Tsz + t)) * 32;
            float*  cout = g_c  + so * 512;
            ushort* hho  = g_hh + so * 512;
            float* ccur = cring + (t & 1) * 1024;
            float* cprv = cring + ((t & 1) ^ 1) * 1024;
            if (layer == 0) {
                float cvv[2];
                #pragma unroll
                for (int n = 0; n < 2; n++) {
                    int it = tid + n * NTHR;
                    int b = it >> 5, jj = it & 31;
                    int j = cta * 32 + jj;
                    float i_ = part[(0 * 32 + jj) * 33 + b];
                    float f_ = part[(1 * 32 + jj) * 33 + b];
                    float gg = part[(2 * 32 + jj) * 33 + b];
                    float o_ = part[(3 * 32 + jj) * 33 + b];
                    float cp = (t > 0) ? cprv[it] : 0.0f;
                    float cv = sigf(i_) * tanhef(gg) + sigf(f_) * cp;
                    float hv = sigf(o_) * tanhef(cv);
                    ccur[it] = cv;
                    hho[(size_t)b * 512 + j] = f16of(hv);
                    cvv[n] = cv;
                }
                __syncthreads();
                if (tid == 0) st_rel(myflagH, (unsigned)(t + 1));
                #pragma unroll
                for (int n = 0; n < 2; n++) {
                    int it = tid + n * NTHR;
                    int b = it >> 5, jj = it & 31;
                    cout[(size_t)b * 512 + cta * 32 + jj] = cvv[n];
                }
                __syncthreads();
                if (tid == 0) st_rel(myflagC, (unsigned)(t + 1));
            } else {
                const float* clow = g_c + (((size_t)(layer - 1) * Tsz + t) * 32) * 512;
                float cvs = 0.0f;
                int b = 0, j = 0;
                const bool has = tid < nj * 32;
                float hvs = 0.0f;
                if (has) {
                    int it = tid;
                    b = it / nj;
                    int jj = it - b * nj;
                    j = j0 + jj;
                    #define RED(SL, B) (part[(SL) * 33 + (B)] + part[PSTR + (SL) * 33 + (B)])
                    float i_ = RED(0 * nj + jj, b);
                    float fp = RED(1 * nj + jj, b);
                    float fl = RED(2 * nj + jj, b);
                    float u_ = RED(3 * nj + jj, b);
                    float o_ = RED(4 * nj + jj, b);
                    #undef RED
                    float cp = (t > 0) ? cprv[tid] : 0.0f;
                    float cl = __ldcg(clow + (size_t)b * 512 + j);
                    cvs = cp * sigf(fp + 1.0f) + cl * sigf(fl + 1.0f) + tanhef(u_) * sigf(i_);
                    hvs = sigf(o_) * tanhef(cvs);
                    ccur[tid] = cvs;
                    hho[(size_t)b * 512 + j] = f16of(hvs);
                }
                __syncthreads();
                if (tid == 0) st_rel(myflagH, (unsigned)(t + 1));
                if (layer != 3) {
                    if (has) cout[(size_t)b * 512 + j] = cvs;
                    __syncthreads();
                    if (tid == 0) st_rel(myflagC, (unsigned)(t + 1));
                } else if (has) {
                    out[(size_t)b * Tsz * Hsz + (size_t)t * Hsz + j] = hvs;
                    out[BTHn + (size_t)b * Tsz * Hsz + (size_t)t * Hsz + j] = cvs;
                    if (t == Tsz - 1) {
                        out[2 * BTHn + (size_t)b * Hsz + j] = hvs;
                        out[2 * BTHn + (size_t)Bsz * Hsz + (size_t)b * Hsz + j] = cvs;
                    }
                }
            }
        }
    }
}

extern "C" void kernel_launch(void* const* d_in, const int* in_sizes, int n_in,
                              void* d_out, int out_size)
{
    const float* x    = (const float*)d_in[0];
    const float* w_ih = (const float*)d_in[1];
    const float* w_hh = (const float*)d_in[2];
    const float* b_ih = (const float*)d_in[3];
    const float* b_hh = (const float*)d_in[4];
    const float* ca_w = (const float*)d_in[5];
    const float* ca_b = (const float*)d_in[6];
    float* out = (float*)d_out;
    (void)in_sizes; (void)n_in; (void)out_size;

    k_fill<<<296, 256>>>(w_hh, ca_w);

    dim3 g(G4 / 64, (Tsz * Bsz) / 64);
    k_xproj<<<g, 256>>>(x, w_ih, b_ih, b_hh);

    const int smem_bytes = CRING_OFF + 2 * 1024 * 4;  // 108032
    cudaFuncSetAttribute(k_wave, cudaFuncAttributeMaxDynamicSharedMemorySize, smem_bytes);
    k_wave<<<NCTA, NTHR, smem_bytes>>>(ca_b, out);
}